// round 6
// baseline (speedup 1.0000x reference)
#include <cuda_runtime.h>
#include <cstdint>

#define NMAX 100000
#define EMAX 1700000
#define HID 64
#define TEDGE 16
typedef unsigned long long ULL;

// Per-node affine precompute:
// A[n] = x[n] @ W1[0:13] + pos[n] @ W1[13:16] + b1
// B[n] = pos[n] @ W1[13:16]
// edge msg hidden: t = relu(A[src]-B[dst]); out[dst] = relu(max_e (t @ W2 + b2))
__device__ __align__(16) float g_A[NMAX * HID];
__device__ __align__(16) float g_B[NMAX * HID];
__device__ int g_cnt[NMAX];
__device__ int g_off[NMAX];
__device__ int g_cur[NMAX];
__device__ int g_srcs[EMAX];   // CSR src ids grouped (sorted) by dst
__device__ int g_dsts[EMAX];   // dst id per CSR slot
__device__ int g_bsum[128];
__device__ int g_is32;

// ---------------- edge dtype detection ----------------
__global__ void detect_kernel(const int* __restrict__ e, long long n_words) {
    __shared__ int any;
    if (threadIdx.x == 0) any = 0;
    __syncthreads();
    long long lim = n_words < 4096 ? n_words : 4096;
    for (long long i = 1 + 2 * (long long)threadIdx.x; i < lim; i += 2 * blockDim.x)
        if (e[i] != 0) any = 1;
    __syncthreads();
    if (threadIdx.x == 0) g_is32 = any;
}
__device__ __forceinline__ int load_idx(const void* e, long long E,
                                        long long i, int which, int is32) {
    if (is32) return ((const int*)e)[which * E + i];
    return (int)((const long long*)e)[which * E + i];
}

// ---------------- per-node precompute ----------------
__global__ __launch_bounds__(256) void precompute_kernel(
    const float* __restrict__ x, const float* __restrict__ pos,
    const float* __restrict__ W1, const float* __restrict__ b1, int n_nodes)
{
    __shared__ float m[16][16];
    __shared__ float W1s[16 * 64];
    __shared__ float b1s[64];
    int tid = threadIdx.x;
    int node0 = blockIdx.x * 16;
    {
        int nl = tid >> 4, f = tid & 15;
        int node = node0 + nl;
        float v = 0.0f;
        if (node < n_nodes)
            v = (f < 13) ? x[node * 13 + f] : pos[node * 3 + (f - 13)];
        m[nl][f] = v;
    }
    #pragma unroll
    for (int j = 0; j < 4; j++) W1s[tid + j * 256] = W1[tid + j * 256];
    if (tid < 64) b1s[tid] = b1[tid];
    __syncthreads();
    int col = tid & 63;
    #pragma unroll
    for (int r = 0; r < 4; r++) {
        int nloc = r * 4 + (tid >> 6);
        int node = node0 + nloc;
        if (node >= n_nodes) continue;
        float accA = b1s[col], accB = 0.0f;
        #pragma unroll
        for (int i = 0; i < 13; i++)
            accA = fmaf(m[nloc][i], W1s[i * 64 + col], accA);
        #pragma unroll
        for (int p = 0; p < 3; p++) {
            float wv = W1s[(13 + p) * 64 + col];
            float pv = m[nloc][13 + p];
            accA = fmaf(pv, wv, accA);
            accB = fmaf(pv, wv, accB);
        }
        g_A[node * 64 + col] = accA;
        g_B[node * 64 + col] = accB;
    }
}

// ---------------- CSR build ----------------
__global__ void zero_cnt_kernel(int n) {
    int i = blockIdx.x * blockDim.x + threadIdx.x;
    if (i < n) g_cnt[i] = 0;
}
__global__ void zero_out_kernel(float* __restrict__ out, int n) {
    int i = blockIdx.x * blockDim.x + threadIdx.x;
    if (i < n) out[i] = 0.0f;
}
__global__ void hist_kernel(const void* __restrict__ e, long long E) {
    long long i = (long long)blockIdx.x * blockDim.x + threadIdx.x;
    if (i < E) atomicAdd(&g_cnt[load_idx(e, E, i, 1, g_is32)], 1);
}
__global__ __launch_bounds__(1024) void scan1_kernel(int n) {
    __shared__ int sm[1024];
    int t = threadIdx.x;
    int idx = blockIdx.x * 1024 + t;
    int v = (idx < n) ? g_cnt[idx] : 0;
    sm[t] = v;
    __syncthreads();
    #pragma unroll
    for (int d = 1; d < 1024; d <<= 1) {
        int u = (t >= d) ? sm[t - d] : 0;
        __syncthreads();
        if (t >= d) sm[t] += u;
        __syncthreads();
    }
    if (idx < n) g_off[idx] = sm[t] - v;
    if (t == 1023) g_bsum[blockIdx.x] = sm[t];
}
__global__ __launch_bounds__(1024) void scan2_kernel(int nb) {
    __shared__ int sm[1024];
    int t = threadIdx.x;
    int v = (t < nb) ? g_bsum[t] : 0;
    sm[t] = v;
    __syncthreads();
    #pragma unroll
    for (int d = 1; d < 1024; d <<= 1) {
        int u = (t >= d) ? sm[t - d] : 0;
        __syncthreads();
        if (t >= d) sm[t] += u;
        __syncthreads();
    }
    if (t < nb) g_bsum[t] = sm[t] - v;
}
__global__ void scan3_kernel(int n) {
    int i = blockIdx.x * blockDim.x + threadIdx.x;
    if (i < n) {
        int o = g_off[i] + g_bsum[i >> 10];
        g_off[i] = o;
        g_cur[i] = o;
    }
}
__global__ void scatter_kernel(const void* __restrict__ e, long long E) {
    long long i = (long long)blockIdx.x * blockDim.x + threadIdx.x;
    if (i < E) {
        int is32 = g_is32;
        int s = load_idx(e, E, i, 0, is32);
        int d = load_idx(e, E, i, 1, is32);
        int p = atomicAdd(&g_cur[d], 1);
        if (p < EMAX) { g_srcs[p] = s; g_dsts[p] = d; }
    }
}
__global__ void pad_kernel(long long E, int n_pad) {
    int i = blockIdx.x * blockDim.x + threadIdx.x;
    if (i < n_pad && E + i < EMAX) g_dsts[E + i] = -1;
}

// ---------------- flat-tile aggregation ----------------
// Packed dual-fp32 FMA (sm_100+)
__device__ __forceinline__ void fma2(ULL& d, ULL a, ULL b) {
    asm("fma.rn.f32x2 %0, %1, %2, %0;" : "+l"(d) : "l"(a), "l"(b));
}
__device__ __forceinline__ float lo32(ULL a) { return __uint_as_float((unsigned)a); }
__device__ __forceinline__ float hi32(ULL a) { return __uint_as_float((unsigned)(a >> 32)); }

#define AGG_BLOCKS 296
#define SM_W2   (64 * 68)
#define SM_TS   (TEDGE * 64)
#define SMEM_AGG ((SM_W2 + 8 * SM_TS) * 4)

// Each warp: one 16-edge flat tile of the dst-sorted CSR stream.
// Lane owns output cols (lane, lane+32). acc[16][2] ULL (f32x2 pairs).
// Segmented max over sorted dst runs, predicated int-atomicMax at run ends.
__global__ __launch_bounds__(256) void agg_flat_kernel(
    const float* __restrict__ W2, const float* __restrict__ b2,
    float* __restrict__ out, long long E, int n_tiles)
{
    extern __shared__ __align__(16) float dyn[];
    float* W2t = dyn;                 // [col][k], pad 68 (conflict-free .128 phases)
    float* tsm = dyn + SM_W2;         // 8 warps x [16 edges][64 k]
    int tid = threadIdx.x;

    for (int i = tid; i < 4096; i += 256) {
        int k = i >> 6, c = i & 63;
        W2t[c * 68 + k] = W2[i];
    }
    __syncthreads();

    int lane = tid & 31, w = tid >> 5;
    float* ts = tsm + w * SM_TS;
    float bc0 = b2[lane], bc1 = b2[lane + 32];
    const ULL* wp0 = (const ULL*)&W2t[lane * 68];
    const ULL* wp1 = (const ULL*)&W2t[(lane + 32) * 68];

    int gw = blockIdx.x * 8 + w;
    int nw = AGG_BLOCKS * 8;

    for (int tile = gw; tile < n_tiles; tile += nw) {
        long long base = (long long)tile * TEDGE;
        // lanes 0-15 carry src, lanes 16-31 carry dst of edge (lane&15)
        int e16 = lane & 15;
        long long gi = base + e16;
        int sd;
        if (lane < 16) sd = (gi < E) ? g_srcs[gi] : 0;
        else           sd = (gi < E) ? g_dsts[gi] : -1;

        #pragma unroll
        for (int e = 0; e < TEDGE; e++) {
            int s = __shfl_sync(0xffffffffu, sd, e);
            int d = __shfl_sync(0xffffffffu, sd, 16 + e);
            float2 t2 = make_float2(0.0f, 0.0f);
            if (d >= 0) {
                float2 av = *(const float2*)&g_A[(size_t)s * 64 + 2 * lane];
                float2 bv = *(const float2*)&g_B[(size_t)d * 64 + 2 * lane];
                t2.x = fmaxf(av.x - bv.x, 0.0f);
                t2.y = fmaxf(av.y - bv.y, 0.0f);
            }
            *(float2*)&ts[e * 64 + 2 * lane] = t2;
        }
        __syncwarp();

        ULL acc[TEDGE][2];
        #pragma unroll
        for (int e = 0; e < TEDGE; e++) { acc[e][0] = 0ull; acc[e][1] = 0ull; }

        #pragma unroll
        for (int k4 = 0; k4 < 16; k4++) {
            ULL w00 = wp0[2 * k4], w01 = wp0[2 * k4 + 1];
            ULL w10 = wp1[2 * k4], w11 = wp1[2 * k4 + 1];
            #pragma unroll
            for (int e = 0; e < TEDGE; e++) {
                const ULL* t2 = (const ULL*)&ts[e * 64 + 4 * k4];
                ULL ta = t2[0], tb = t2[1];
                fma2(acc[e][0], ta, w00); fma2(acc[e][0], tb, w01);
                fma2(acc[e][1], ta, w10); fma2(acc[e][1], tb, w11);
            }
        }

        // segmented max over sorted dsts; last edge of tile always flushes
        float run0 = -1e30f, run1 = -1e30f;
        #pragma unroll
        for (int e = 0; e < TEDGE; e++) {
            int d  = __shfl_sync(0xffffffffu, sd, 16 + e);
            int dn = (e < TEDGE - 1) ? __shfl_sync(0xffffffffu, sd, 17 + e) : -2;
            float v0 = lo32(acc[e][0]) + hi32(acc[e][0]);
            float v1 = lo32(acc[e][1]) + hi32(acc[e][1]);
            run0 = fmaxf(run0, v0);
            run1 = fmaxf(run1, v1);
            if (d != dn) {
                if (d >= 0) {
                    float f0 = run0 + bc0, f1 = run1 + bc1;
                    // out >= 0 always; positive-float int compare == float compare
                    if (f0 > 0.0f)
                        atomicMax((int*)(out + (size_t)d * 64 + lane),
                                  __float_as_int(f0));
                    if (f1 > 0.0f)
                        atomicMax((int*)(out + (size_t)d * 64 + 32 + lane),
                                  __float_as_int(f1));
                }
                run0 = -1e30f;
                run1 = -1e30f;
            }
        }
        __syncwarp();   // ts reused next tile
    }
}

extern "C" void kernel_launch(void* const* d_in, const int* in_sizes, int n_in,
                              void* d_out, int out_size) {
    const float* x   = (const float*)d_in[0];
    const float* pos = (const float*)d_in[1];
    const float* W1  = (const float*)d_in[2];
    const float* b1  = (const float*)d_in[3];
    const float* W2  = (const float*)d_in[4];
    const float* b2  = (const float*)d_in[5];
    const void*  eidx = d_in[6];

    int n_nodes = in_sizes[0] / 13;
    if (n_nodes > NMAX) n_nodes = NMAX;
    long long E = (long long)in_sizes[6] / 2;
    if (E > EMAX) E = EMAX;
    float* out = (float*)d_out;

    int n_tiles = (int)((E + TEDGE - 1) / TEDGE);
    int n_pad = n_tiles * TEDGE - (int)E;
    int nb_nodes = (n_nodes + 255) / 256;
    int nb_edges = (int)((E + 255) / 256);
    int nb_scan  = (n_nodes + 1023) / 1024;

    cudaFuncSetAttribute(agg_flat_kernel,
                         cudaFuncAttributeMaxDynamicSharedMemorySize, SMEM_AGG);

    detect_kernel<<<1, 256>>>((const int*)eidx, 2 * E);
    precompute_kernel<<<(n_nodes + 15) / 16, 256>>>(x, pos, W1, b1, n_nodes);
    zero_cnt_kernel<<<nb_nodes, 256>>>(n_nodes);
    zero_out_kernel<<<(out_size + 255) / 256, 256>>>(out, out_size);
    hist_kernel<<<nb_edges, 256>>>(eidx, E);
    scan1_kernel<<<nb_scan, 1024>>>(n_nodes);
    scan2_kernel<<<1, 1024>>>(nb_scan);
    scan3_kernel<<<nb_nodes, 256>>>(n_nodes);
    scatter_kernel<<<nb_edges, 256>>>(eidx, E);
    if (n_pad > 0) pad_kernel<<<1, 256>>>(E, n_pad);
    agg_flat_kernel<<<AGG_BLOCKS, 256, SMEM_AGG>>>(W2, b2, out, E, n_tiles);
}

// round 7
// speedup vs baseline: 1.6154x; 1.6154x over previous
#include <cuda_runtime.h>
#include <cuda_bf16.h>
#include <cstdint>

#define NMAX 100000
#define EMAX 1700000
#define HID 64
#define TEDGE 32
typedef unsigned long long ULL;

// Per-node affine precompute:
// A[n] = x[n] @ W1[0:13] + pos[n] @ W1[13:16] + b1
// B[n] = pos[n] @ W1[13:16]
// edge msg hidden: t = relu(A[src]-B[dst]); out[dst] = relu(max_e (t @ W2 + b2))
__device__ __align__(16) float g_A[NMAX * HID];
__device__ __align__(16) float g_B[NMAX * HID];
__device__ int g_cnt[NMAX];
__device__ int g_off[NMAX];
__device__ int g_cur[NMAX];
__device__ int g_srcs[EMAX];   // CSR src ids grouped (sorted) by dst
__device__ int g_dsts[EMAX];   // dst id per CSR slot (+ -1 padding)
__device__ int g_bsum[128];
__device__ int g_is32;

// ---------------- edge dtype detection ----------------
__global__ void detect_kernel(const int* __restrict__ e, long long n_words) {
    __shared__ int any;
    if (threadIdx.x == 0) any = 0;
    __syncthreads();
    long long lim = n_words < 4096 ? n_words : 4096;
    for (long long i = 1 + 2 * (long long)threadIdx.x; i < lim; i += 2 * blockDim.x)
        if (e[i] != 0) any = 1;
    __syncthreads();
    if (threadIdx.x == 0) g_is32 = any;
}
__device__ __forceinline__ int load_idx(const void* e, long long E,
                                        long long i, int which, int is32) {
    if (is32) return ((const int*)e)[which * E + i];
    return (int)((const long long*)e)[which * E + i];
}

// ---------------- per-node precompute ----------------
__global__ __launch_bounds__(256) void precompute_kernel(
    const float* __restrict__ x, const float* __restrict__ pos,
    const float* __restrict__ W1, const float* __restrict__ b1, int n_nodes)
{
    __shared__ float m[16][16];
    __shared__ float W1s[16 * 64];
    __shared__ float b1s[64];
    int tid = threadIdx.x;
    int node0 = blockIdx.x * 16;
    {
        int nl = tid >> 4, f = tid & 15;
        int node = node0 + nl;
        float v = 0.0f;
        if (node < n_nodes)
            v = (f < 13) ? x[node * 13 + f] : pos[node * 3 + (f - 13)];
        m[nl][f] = v;
    }
    #pragma unroll
    for (int j = 0; j < 4; j++) W1s[tid + j * 256] = W1[tid + j * 256];
    if (tid < 64) b1s[tid] = b1[tid];
    __syncthreads();
    int col = tid & 63;
    #pragma unroll
    for (int r = 0; r < 4; r++) {
        int nloc = r * 4 + (tid >> 6);
        int node = node0 + nloc;
        if (node >= n_nodes) continue;
        float accA = b1s[col], accB = 0.0f;
        #pragma unroll
        for (int i = 0; i < 13; i++)
            accA = fmaf(m[nloc][i], W1s[i * 64 + col], accA);
        #pragma unroll
        for (int p = 0; p < 3; p++) {
            float wv = W1s[(13 + p) * 64 + col];
            float pv = m[nloc][13 + p];
            accA = fmaf(pv, wv, accA);
            accB = fmaf(pv, wv, accB);
        }
        g_A[node * 64 + col] = accA;
        g_B[node * 64 + col] = accB;
    }
}

// ---------------- CSR build ----------------
__global__ void zero_cnt_kernel(int n) {
    int i = blockIdx.x * blockDim.x + threadIdx.x;
    if (i < n) g_cnt[i] = 0;
}
__global__ void zero_out_kernel(float* __restrict__ out, int n) {
    int i = blockIdx.x * blockDim.x + threadIdx.x;
    if (i < n) out[i] = 0.0f;
}
__global__ void hist_kernel(const void* __restrict__ e, long long E) {
    long long i = (long long)blockIdx.x * blockDim.x + threadIdx.x;
    if (i < E) atomicAdd(&g_cnt[load_idx(e, E, i, 1, g_is32)], 1);
}
__global__ __launch_bounds__(1024) void scan1_kernel(int n) {
    __shared__ int sm[1024];
    int t = threadIdx.x;
    int idx = blockIdx.x * 1024 + t;
    int v = (idx < n) ? g_cnt[idx] : 0;
    sm[t] = v;
    __syncthreads();
    #pragma unroll
    for (int d = 1; d < 1024; d <<= 1) {
        int u = (t >= d) ? sm[t - d] : 0;
        __syncthreads();
        if (t >= d) sm[t] += u;
        __syncthreads();
    }
    if (idx < n) g_off[idx] = sm[t] - v;
    if (t == 1023) g_bsum[blockIdx.x] = sm[t];
}
__global__ __launch_bounds__(1024) void scan2_kernel(int nb) {
    __shared__ int sm[1024];
    int t = threadIdx.x;
    int v = (t < nb) ? g_bsum[t] : 0;
    sm[t] = v;
    __syncthreads();
    #pragma unroll
    for (int d = 1; d < 1024; d <<= 1) {
        int u = (t >= d) ? sm[t - d] : 0;
        __syncthreads();
        if (t >= d) sm[t] += u;
        __syncthreads();
    }
    if (t < nb) g_bsum[t] = sm[t] - v;
}
__global__ void scan3_kernel(int n) {
    int i = blockIdx.x * blockDim.x + threadIdx.x;
    if (i < n) {
        int o = g_off[i] + g_bsum[i >> 10];
        g_off[i] = o;
        g_cur[i] = o;
    }
}
__global__ void scatter_kernel(const void* __restrict__ e, long long E) {
    long long i = (long long)blockIdx.x * blockDim.x + threadIdx.x;
    if (i < E) {
        int is32 = g_is32;
        int s = load_idx(e, E, i, 0, is32);
        int d = load_idx(e, E, i, 1, is32);
        int p = atomicAdd(&g_cur[d], 1);
        if (p < EMAX) { g_srcs[p] = s; g_dsts[p] = d; }
    }
}
__global__ void pad_kernel(long long E, int n_pad) {
    int i = blockIdx.x * blockDim.x + threadIdx.x;
    if (i < n_pad && E + i < EMAX) g_dsts[E + i] = -1;
}

// ---------------- mma.sync helpers ----------------
__device__ __forceinline__ uint32_t smem_u32(const void* p) {
    uint32_t a;
    asm("{ .reg .u64 t; cvta.to.shared.u64 t, %1; cvt.u32.u64 %0, t; }"
        : "=r"(a) : "l"(p));
    return a;
}
__device__ __forceinline__ void ldsm4(uint32_t* a, uint32_t addr) {
    asm volatile("ldmatrix.sync.aligned.m8n8.x4.shared.b16 {%0,%1,%2,%3}, [%4];"
                 : "=r"(a[0]), "=r"(a[1]), "=r"(a[2]), "=r"(a[3]) : "r"(addr));
}
__device__ __forceinline__ void ldsm2(uint32_t* b, uint32_t addr) {
    asm volatile("ldmatrix.sync.aligned.m8n8.x2.shared.b16 {%0,%1}, [%2];"
                 : "=r"(b[0]), "=r"(b[1]) : "r"(addr));
}
__device__ __forceinline__ void mma16816(float* c, const uint32_t* a, const uint32_t* b) {
    asm volatile(
        "mma.sync.aligned.m16n8k16.row.col.f32.bf16.bf16.f32 "
        "{%0,%1,%2,%3}, {%4,%5,%6,%7}, {%8,%9}, {%0,%1,%2,%3};"
        : "+f"(c[0]), "+f"(c[1]), "+f"(c[2]), "+f"(c[3])
        : "r"(a[0]), "r"(a[1]), "r"(a[2]), "r"(a[3]), "r"(b[0]), "r"(b[1]));
}
// pack two f32 -> bf16x2, low halfword = lo_f
__device__ __forceinline__ uint32_t packbf(float lo_f, float hi_f) {
    uint32_t r;
    asm("cvt.rn.bf16x2.f32 %0, %1, %2;" : "=r"(r) : "f"(hi_f), "f"(lo_f));
    return r;
}

// ---------------- mma aggregation ----------------
// smem: W_cat 64 rows x 400B = 25600B; per-warp t rows 32 x 400B = 12800B
// t region reused as red[32][68] f32 during the scan phase.
#define WROW 400
#define SM_W (64 * WROW)
#define SM_T (32 * WROW)
#define SMEM_AGG (SM_W + 8 * SM_T)
#define AGG_GRID 148

__global__ __launch_bounds__(256, 1) void mma_agg_kernel(
    const float* __restrict__ W2, const float* __restrict__ b2,
    float* __restrict__ out, long long E, int n_tiles)
{
    extern __shared__ __align__(16) char smem[];
    char* wbuf = smem;
    int tid = threadIdx.x;
    int lane = tid & 31, w = tid >> 5;
    char* tbuf = smem + SM_W + w * SM_T;

    // Stage W_cat[n][k]: k-blocks [hi(0..63) | hi(64..127) | lo(128..191)]
    for (int i = tid; i < 4096; i += 256) {
        int k = i >> 6, n = i & 63;
        float wv = W2[i];
        __nv_bfloat16 h = __float2bfloat16(wv);
        float hf = __bfloat162float(h);
        __nv_bfloat16 l = __float2bfloat16(wv - hf);
        unsigned short hu = __bfloat16_as_ushort(h);
        unsigned short lu = __bfloat16_as_ushort(l);
        *(unsigned short*)(wbuf + n * WROW + k * 2)       = hu;
        *(unsigned short*)(wbuf + n * WROW + 128 + k * 2) = hu;
        *(unsigned short*)(wbuf + n * WROW + 256 + k * 2) = lu;
    }
    __syncthreads();

    uint32_t wsm = smem_u32(wbuf);
    uint32_t tsm = smem_u32(tbuf);
    float* red = (float*)tbuf;              // [32][68] alias
    float bias0 = b2[2 * lane], bias1 = b2[2 * lane + 1];

    // ldmatrix A addresses: lane group g=l>>3: row=(l&7)+8*(g&1), koff=(g>>1)*16B
    uint32_t a_row  = (uint32_t)((lane & 7) + ((lane >> 3) & 1) * 8);
    uint32_t a_koff = (uint32_t)((lane >> 4) * 16);
    // ldmatrix B addresses (x2, lanes 0-15): n=(l&7), koff=((l>>3)&1)*16B
    uint32_t b_nrow = (uint32_t)(lane & 7);
    uint32_t b_koff = (uint32_t)(((lane >> 3) & 1) * 16);

    int gw = blockIdx.x * 8 + w;
    int nw = AGG_GRID * 8;

    for (int tile = gw; tile < n_tiles; tile += nw) {
        long long gi = (long long)tile * TEDGE + lane;
        int d = g_dsts[gi];                 // padded with -1 past E
        int mydst = d;

        // ---- stage t row: [hi(64) | lo(64) | hi(64)] bf16 ----
        uint32_t hi[32], lo[32];
        if (d >= 0) {
            int s = g_srcs[gi];
            const float4* ap = (const float4*)(g_A + (size_t)s * 64);
            const float4* bp = (const float4*)(g_B + (size_t)d * 64);
            #pragma unroll
            for (int q = 0; q < 16; q++) {
                float4 a = ap[q], b = bp[q];
                float t0 = fmaxf(a.x - b.x, 0.0f);
                float t1 = fmaxf(a.y - b.y, 0.0f);
                float t2 = fmaxf(a.z - b.z, 0.0f);
                float t3 = fmaxf(a.w - b.w, 0.0f);
                uint32_t hp0 = packbf(t0, t1);
                uint32_t hp1 = packbf(t2, t3);
                hi[2 * q]     = hp0;
                hi[2 * q + 1] = hp1;
                float hf0 = __uint_as_float(hp0 << 16);
                float hf1 = __uint_as_float(hp0 & 0xffff0000u);
                float hf2 = __uint_as_float(hp1 << 16);
                float hf3 = __uint_as_float(hp1 & 0xffff0000u);
                lo[2 * q]     = packbf(t0 - hf0, t1 - hf1);
                lo[2 * q + 1] = packbf(t2 - hf2, t3 - hf3);
            }
        } else {
            #pragma unroll
            for (int q = 0; q < 32; q++) { hi[q] = 0u; lo[q] = 0u; }
        }
        {
            char* trow = tbuf + lane * WROW;
            #pragma unroll
            for (int j = 0; j < 8; j++) {
                *(uint4*)(trow + j * 16) =
                    make_uint4(hi[4 * j], hi[4 * j + 1], hi[4 * j + 2], hi[4 * j + 3]);
                *(uint4*)(trow + 128 + j * 16) =
                    make_uint4(lo[4 * j], lo[4 * j + 1], lo[4 * j + 2], lo[4 * j + 3]);
                *(uint4*)(trow + 256 + j * 16) =
                    make_uint4(hi[4 * j], hi[4 * j + 1], hi[4 * j + 2], hi[4 * j + 3]);
            }
        }
        __syncwarp();

        // ---- GEMM: 32 edges x 64 cols, K=192 ----
        float c[2][8][4];
        #pragma unroll
        for (int mt = 0; mt < 2; mt++)
            #pragma unroll
            for (int nt = 0; nt < 8; nt++)
                #pragma unroll
                for (int q = 0; q < 4; q++) c[mt][nt][q] = 0.0f;

        #pragma unroll
        for (int ks = 0; ks < 12; ks++) {
            uint32_t afr[2][4];
            uint32_t abase = tsm + a_row * WROW + (uint32_t)ks * 32 + a_koff;
            ldsm4(afr[0], abase);
            ldsm4(afr[1], abase + 16u * WROW);
            #pragma unroll
            for (int nt = 0; nt < 8; nt++) {
                uint32_t bfr[2];
                ldsm2(bfr, wsm + ((uint32_t)nt * 8 + b_nrow) * WROW +
                            (uint32_t)ks * 32 + b_koff);
                mma16816(c[0][nt], afr[0], bfr);
                mma16816(c[1][nt], afr[1], bfr);
            }
        }
        __syncwarp();   // all ldmatrix reads of tbuf done before red overwrite

        // ---- C -> red[edge][col] (row pad 68) ----
        {
            int r0 = lane >> 2;
            int c0 = 2 * (lane & 3);
            #pragma unroll
            for (int mt = 0; mt < 2; mt++)
                #pragma unroll
                for (int nt = 0; nt < 8; nt++) {
                    int col = nt * 8 + c0;
                    *(float2*)&red[(mt * 16 + r0) * 68 + col] =
                        make_float2(c[mt][nt][0], c[mt][nt][1]);
                    *(float2*)&red[(mt * 16 + r0 + 8) * 68 + col] =
                        make_float2(c[mt][nt][2], c[mt][nt][3]);
                }
        }
        __syncwarp();

        // ---- segmented max over sorted dsts; lane owns cols 2l, 2l+1 ----
        {
            float run0 = -1e30f, run1 = -1e30f;
            bool first_run = true;
            #pragma unroll
            for (int e = 0; e < TEDGE; e++) {
                int de = __shfl_sync(0xffffffffu, mydst, e);
                int dn = (e < TEDGE - 1) ? __shfl_sync(0xffffffffu, mydst, e + 1) : -2;
                float2 v = *(const float2*)&red[e * 68 + 2 * lane];
                run0 = fmaxf(run0, v.x);
                run1 = fmaxf(run1, v.y);
                if (de != dn) {
                    if (de >= 0) {
                        float f0 = run0 + bias0, f1 = run1 + bias1;
                        bool boundary = first_run || (e == TEDGE - 1);
                        if (boundary) {
                            if (f0 > 0.0f)
                                atomicMax((int*)(out + (size_t)de * 64 + 2 * lane),
                                          __float_as_int(f0));
                            if (f1 > 0.0f)
                                atomicMax((int*)(out + (size_t)de * 64 + 2 * lane + 1),
                                          __float_as_int(f1));
                        } else {
                            *(float2*)(out + (size_t)de * 64 + 2 * lane) =
                                make_float2(fmaxf(f0, 0.0f), fmaxf(f1, 0.0f));
                        }
                    }
                    run0 = -1e30f;
                    run1 = -1e30f;
                    first_run = false;
                }
            }
        }
        __syncwarp();   // tbuf/red reused next tile
    }
}

extern "C" void kernel_launch(void* const* d_in, const int* in_sizes, int n_in,
                              void* d_out, int out_size) {
    const float* x   = (const float*)d_in[0];
    const float* pos = (const float*)d_in[1];
    const float* W1  = (const float*)d_in[2];
    const float* b1  = (const float*)d_in[3];
    const float* W2  = (const float*)d_in[4];
    const float* b2  = (const float*)d_in[5];
    const void*  eidx = d_in[6];

    int n_nodes = in_sizes[0] / 13;
    if (n_nodes > NMAX) n_nodes = NMAX;
    long long E = (long long)in_sizes[6] / 2;
    if (E > EMAX - TEDGE) E = EMAX - TEDGE;
    float* out = (float*)d_out;

    int n_tiles = (int)((E + TEDGE - 1) / TEDGE);
    int n_pad = n_tiles * TEDGE - (int)E;
    int nb_nodes = (n_nodes + 255) / 256;
    int nb_edges = (int)((E + 255) / 256);
    int nb_scan  = (n_nodes + 1023) / 1024;

    cudaFuncSetAttribute(mma_agg_kernel,
                         cudaFuncAttributeMaxDynamicSharedMemorySize, SMEM_AGG);

    detect_kernel<<<1, 256>>>((const int*)eidx, 2 * E);
    precompute_kernel<<<(n_nodes + 15) / 16, 256>>>(x, pos, W1, b1, n_nodes);
    zero_cnt_kernel<<<nb_nodes, 256>>>(n_nodes);
    zero_out_kernel<<<(out_size + 255) / 256, 256>>>(out, out_size);
    hist_kernel<<<nb_edges, 256>>>(eidx, E);
    scan1_kernel<<<nb_scan, 1024>>>(n_nodes);
    scan2_kernel<<<1, 1024>>>(nb_scan);
    scan3_kernel<<<nb_nodes, 256>>>(n_nodes);
    scatter_kernel<<<nb_edges, 256>>>(eidx, E);
    if (n_pad > 0) pad_kernel<<<1, 256>>>(E, n_pad);
    mma_agg_kernel<<<AGG_GRID, 256, SMEM_AGG>>>(W2, b2, out, E, n_tiles);
}

// round 8
// speedup vs baseline: 1.9389x; 1.2003x over previous
#include <cuda_runtime.h>
#include <cuda_bf16.h>
#include <cstdint>

#define NMAX 100000
#define EMAX 1700000
#define HID 64
#define TEDGE 32
typedef unsigned long long ULL;

// Per-node affine precompute:
// A[n] = x[n] @ W1[0:13] + pos[n] @ W1[13:16] + b1
// B[n] = pos[n] @ W1[13:16]
// edge msg hidden: t = relu(A[src]-B[dst]); out[dst] = relu(max_e (t @ W2 + b2))
__device__ __align__(16) float g_A[NMAX * HID];
__device__ __align__(16) float g_B[NMAX * HID];
__device__ int g_cnt[NMAX];
__device__ int g_off[NMAX];
__device__ int g_cur[NMAX];
__device__ int g_srcs[EMAX];   // CSR src ids grouped (sorted) by dst
__device__ int g_dsts[EMAX];   // dst id per CSR slot (+ -1 padding)
__device__ int g_bsum[128];
__device__ int g_is32;

// ---------------- edge dtype detection ----------------
__global__ void detect_kernel(const int* __restrict__ e, long long n_words) {
    __shared__ int any;
    if (threadIdx.x == 0) any = 0;
    __syncthreads();
    long long lim = n_words < 4096 ? n_words : 4096;
    for (long long i = 1 + 2 * (long long)threadIdx.x; i < lim; i += 2 * blockDim.x)
        if (e[i] != 0) any = 1;
    __syncthreads();
    if (threadIdx.x == 0) g_is32 = any;
}
__device__ __forceinline__ int load_idx(const void* e, long long E,
                                        long long i, int which, int is32) {
    if (is32) return ((const int*)e)[which * E + i];
    return (int)((const long long*)e)[which * E + i];
}

// ---------------- per-node precompute ----------------
__global__ __launch_bounds__(256) void precompute_kernel(
    const float* __restrict__ x, const float* __restrict__ pos,
    const float* __restrict__ W1, const float* __restrict__ b1, int n_nodes)
{
    __shared__ float m[16][16];
    __shared__ float W1s[16 * 64];
    __shared__ float b1s[64];
    int tid = threadIdx.x;
    int node0 = blockIdx.x * 16;
    {
        int nl = tid >> 4, f = tid & 15;
        int node = node0 + nl;
        float v = 0.0f;
        if (node < n_nodes)
            v = (f < 13) ? x[node * 13 + f] : pos[node * 3 + (f - 13)];
        m[nl][f] = v;
    }
    #pragma unroll
    for (int j = 0; j < 4; j++) W1s[tid + j * 256] = W1[tid + j * 256];
    if (tid < 64) b1s[tid] = b1[tid];
    __syncthreads();
    int col = tid & 63;
    #pragma unroll
    for (int r = 0; r < 4; r++) {
        int nloc = r * 4 + (tid >> 6);
        int node = node0 + nloc;
        if (node >= n_nodes) continue;
        float accA = b1s[col], accB = 0.0f;
        #pragma unroll
        for (int i = 0; i < 13; i++)
            accA = fmaf(m[nloc][i], W1s[i * 64 + col], accA);
        #pragma unroll
        for (int p = 0; p < 3; p++) {
            float wv = W1s[(13 + p) * 64 + col];
            float pv = m[nloc][13 + p];
            accA = fmaf(pv, wv, accA);
            accB = fmaf(pv, wv, accB);
        }
        g_A[node * 64 + col] = accA;
        g_B[node * 64 + col] = accB;
    }
}

// ---------------- CSR build ----------------
__global__ void zero_cnt_kernel(int n) {
    int i = blockIdx.x * blockDim.x + threadIdx.x;
    if (i < n) g_cnt[i] = 0;
}
__global__ void zero_out_kernel(float4* __restrict__ out, int n4) {
    int i = blockIdx.x * blockDim.x + threadIdx.x;
    if (i < n4) out[i] = make_float4(0.0f, 0.0f, 0.0f, 0.0f);
}
__global__ void hist_kernel(const void* __restrict__ e, long long E) {
    long long i = (long long)blockIdx.x * blockDim.x + threadIdx.x;
    if (i < E) atomicAdd(&g_cnt[load_idx(e, E, i, 1, g_is32)], 1);
}
__global__ __launch_bounds__(1024) void scan1_kernel(int n) {
    __shared__ int sm[1024];
    int t = threadIdx.x;
    int idx = blockIdx.x * 1024 + t;
    int v = (idx < n) ? g_cnt[idx] : 0;
    sm[t] = v;
    __syncthreads();
    #pragma unroll
    for (int d = 1; d < 1024; d <<= 1) {
        int u = (t >= d) ? sm[t - d] : 0;
        __syncthreads();
        if (t >= d) sm[t] += u;
        __syncthreads();
    }
    if (idx < n) g_off[idx] = sm[t] - v;
    if (t == 1023) g_bsum[blockIdx.x] = sm[t];
}
__global__ __launch_bounds__(1024) void scan2_kernel(int nb) {
    __shared__ int sm[1024];
    int t = threadIdx.x;
    int v = (t < nb) ? g_bsum[t] : 0;
    sm[t] = v;
    __syncthreads();
    #pragma unroll
    for (int d = 1; d < 1024; d <<= 1) {
        int u = (t >= d) ? sm[t - d] : 0;
        __syncthreads();
        if (t >= d) sm[t] += u;
        __syncthreads();
    }
    if (t < nb) g_bsum[t] = sm[t] - v;
}
__global__ void scan3_kernel(int n) {
    int i = blockIdx.x * blockDim.x + threadIdx.x;
    if (i < n) {
        int o = g_off[i] + g_bsum[i >> 10];
        g_off[i] = o;
        g_cur[i] = o;
    }
}
__global__ void scatter_kernel(const void* __restrict__ e, long long E) {
    long long i = (long long)blockIdx.x * blockDim.x + threadIdx.x;
    if (i < E) {
        int is32 = g_is32;
        int s = load_idx(e, E, i, 0, is32);
        int d = load_idx(e, E, i, 1, is32);
        int p = atomicAdd(&g_cur[d], 1);
        if (p < EMAX) { g_srcs[p] = s; g_dsts[p] = d; }
    }
}
__global__ void pad_kernel(long long E, int n_pad) {
    int i = blockIdx.x * blockDim.x + threadIdx.x;
    if (i < n_pad && E + i < EMAX) g_dsts[E + i] = -1;
}

// ---------------- mma.sync helpers ----------------
__device__ __forceinline__ uint32_t smem_u32(const void* p) {
    uint32_t a;
    asm("{ .reg .u64 t; cvta.to.shared.u64 t, %1; cvt.u32.u64 %0, t; }"
        : "=r"(a) : "l"(p));
    return a;
}
__device__ __forceinline__ void ldsm4(uint32_t* a, uint32_t addr) {
    asm volatile("ldmatrix.sync.aligned.m8n8.x4.shared.b16 {%0,%1,%2,%3}, [%4];"
                 : "=r"(a[0]), "=r"(a[1]), "=r"(a[2]), "=r"(a[3]) : "r"(addr));
}
__device__ __forceinline__ void ldsm2(uint32_t* b, uint32_t addr) {
    asm volatile("ldmatrix.sync.aligned.m8n8.x2.shared.b16 {%0,%1}, [%2];"
                 : "=r"(b[0]), "=r"(b[1]) : "r"(addr));
}
__device__ __forceinline__ void mma16816(float* c, const uint32_t* a, const uint32_t* b) {
    asm volatile(
        "mma.sync.aligned.m16n8k16.row.col.f32.bf16.bf16.f32 "
        "{%0,%1,%2,%3}, {%4,%5,%6,%7}, {%8,%9}, {%0,%1,%2,%3};"
        : "+f"(c[0]), "+f"(c[1]), "+f"(c[2]), "+f"(c[3])
        : "r"(a[0]), "r"(a[1]), "r"(a[2]), "r"(a[3]), "r"(b[0]), "r"(b[1]));
}
// pack two f32 -> bf16x2, low halfword = lo_f
__device__ __forceinline__ uint32_t packbf(float lo_f, float hi_f) {
    uint32_t r;
    asm("cvt.rn.bf16x2.f32 %0, %1, %2;" : "=r"(r) : "f"(hi_f), "f"(lo_f));
    return r;
}

// ---------------- mma aggregation ----------------
// smem: W_cat 64 rows x 400B; per-warp t: 32 rows x 400B (reused as red[32][68] f32)
#define WROW 400
#define SM_W (64 * WROW)
#define SM_T (32 * WROW)
#define NWARP 12
#define SMEM_AGG (SM_W + NWARP * SM_T)
#define AGG_GRID 148

__global__ __launch_bounds__(NWARP * 32, 1) void mma_agg_kernel(
    const float* __restrict__ W2, const float* __restrict__ b2,
    float* __restrict__ out, long long E, int n_tiles)
{
    extern __shared__ __align__(16) char smem[];
    char* wbuf = smem;
    int tid = threadIdx.x;
    int lane = tid & 31, w = tid >> 5;
    char* tbuf = smem + SM_W + w * SM_T;

    // Stage W_cat[n][k]: k-blocks [hi(0..63) | hi(64..127) | lo(128..191)]
    for (int i = tid; i < 4096; i += NWARP * 32) {
        int k = i >> 6, n = i & 63;
        float wv = W2[i];
        __nv_bfloat16 h = __float2bfloat16(wv);
        float hf = __bfloat162float(h);
        __nv_bfloat16 l = __float2bfloat16(wv - hf);
        unsigned short hu = __bfloat16_as_ushort(h);
        unsigned short lu = __bfloat16_as_ushort(l);
        *(unsigned short*)(wbuf + n * WROW + k * 2)       = hu;
        *(unsigned short*)(wbuf + n * WROW + 128 + k * 2) = hu;
        *(unsigned short*)(wbuf + n * WROW + 256 + k * 2) = lu;
    }
    __syncthreads();

    uint32_t wsm = smem_u32(wbuf);
    uint32_t tsm = smem_u32(tbuf);
    float* red = (float*)tbuf;              // [32][68] alias
    float bias0 = b2[2 * lane], bias1 = b2[2 * lane + 1];

    // ldmatrix A: group g=l>>3: row=(l&7)+8*(g&1), koff=(g>>1)*16B
    uint32_t a_row  = (uint32_t)((lane & 7) + ((lane >> 3) & 1) * 8);
    uint32_t a_koff = (uint32_t)((lane >> 4) * 16);
    // ldmatrix B (x2, lanes 0-15): n=(l&7), koff=((l>>3)&1)*16B
    uint32_t b_nrow = (uint32_t)(lane & 7);
    uint32_t b_koff = (uint32_t)(((lane >> 3) & 1) * 16);

    int gw = blockIdx.x * NWARP + w;
    int nw = AGG_GRID * NWARP;

    for (int tile = gw; tile < n_tiles; tile += nw) {
        long long base = (long long)tile * TEDGE;
        int mysrc = g_srcs[base + lane];
        int mydst = g_dsts[base + lane];    // padded with -1 past E

        // ---- cooperative staging: whole warp builds one edge row at a time.
        // lane owns k = 2*lane, 2*lane+1 -> 2 cache lines per row load.
        #pragma unroll
        for (int e = 0; e < TEDGE; e++) {
            int s = __shfl_sync(0xffffffffu, mysrc, e);
            int d = __shfl_sync(0xffffffffu, mydst, e);
            uint32_t hp = 0u, lp = 0u;
            if (d >= 0) {
                float2 a = *(const float2*)(g_A + (size_t)s * 64 + 2 * lane);
                float2 b = *(const float2*)(g_B + (size_t)d * 64 + 2 * lane);
                float t0 = fmaxf(a.x - b.x, 0.0f);
                float t1 = fmaxf(a.y - b.y, 0.0f);
                hp = packbf(t0, t1);
                float hf0 = __uint_as_float(hp << 16);
                float hf1 = __uint_as_float(hp & 0xffff0000u);
                lp = packbf(t0 - hf0, t1 - hf1);
            }
            char* trow = tbuf + e * WROW;
            *(uint32_t*)(trow + 4 * lane)       = hp;   // hi block
            *(uint32_t*)(trow + 128 + 4 * lane) = lp;   // lo block
            *(uint32_t*)(trow + 256 + 4 * lane) = hp;   // hi dup
        }
        __syncwarp();

        // ---- GEMM: 32 edges x 64 cols, K=192 ----
        float c[2][8][4];
        #pragma unroll
        for (int mt = 0; mt < 2; mt++)
            #pragma unroll
            for (int nt = 0; nt < 8; nt++)
                #pragma unroll
                for (int q = 0; q < 4; q++) c[mt][nt][q] = 0.0f;

        #pragma unroll
        for (int ks = 0; ks < 12; ks++) {
            uint32_t afr[2][4];
            uint32_t abase = tsm + a_row * WROW + (uint32_t)ks * 32 + a_koff;
            ldsm4(afr[0], abase);
            ldsm4(afr[1], abase + 16u * WROW);
            #pragma unroll
            for (int nt = 0; nt < 8; nt++) {
                uint32_t bfr[2];
                ldsm2(bfr, wsm + ((uint32_t)nt * 8 + b_nrow) * WROW +
                            (uint32_t)ks * 32 + b_koff);
                mma16816(c[0][nt], afr[0], bfr);
                mma16816(c[1][nt], afr[1], bfr);
            }
        }
        __syncwarp();   // ldmatrix reads done before red overwrite

        // ---- C -> red[edge][col] (row pad 68) ----
        {
            int r0 = lane >> 2;
            int c0 = 2 * (lane & 3);
            #pragma unroll
            for (int mt = 0; mt < 2; mt++)
                #pragma unroll
                for (int nt = 0; nt < 8; nt++) {
                    int col = nt * 8 + c0;
                    *(float2*)&red[(mt * 16 + r0) * 68 + col] =
                        make_float2(c[mt][nt][0], c[mt][nt][1]);
                    *(float2*)&red[(mt * 16 + r0 + 8) * 68 + col] =
                        make_float2(c[mt][nt][2], c[mt][nt][3]);
                }
        }
        __syncwarp();

        // ---- segmented max over sorted dsts; lane owns cols 2l, 2l+1 ----
        {
            float run0 = -1e30f, run1 = -1e30f;
            bool first_run = true;
            #pragma unroll
            for (int e = 0; e < TEDGE; e++) {
                int de = __shfl_sync(0xffffffffu, mydst, e);
                int dn = (e < TEDGE - 1) ? __shfl_sync(0xffffffffu, mydst, e + 1) : -2;
                float2 v = *(const float2*)&red[e * 68 + 2 * lane];
                run0 = fmaxf(run0, v.x);
                run1 = fmaxf(run1, v.y);
                if (de != dn) {
                    if (de >= 0) {
                        float f0 = run0 + bias0, f1 = run1 + bias1;
                        bool boundary = first_run || (e == TEDGE - 1);
                        if (boundary) {
                            if (f0 > 0.0f)
                                atomicMax((int*)(out + (size_t)de * 64 + 2 * lane),
                                          __float_as_int(f0));
                            if (f1 > 0.0f)
                                atomicMax((int*)(out + (size_t)de * 64 + 2 * lane + 1),
                                          __float_as_int(f1));
                        } else {
                            *(float2*)(out + (size_t)de * 64 + 2 * lane) =
                                make_float2(fmaxf(f0, 0.0f), fmaxf(f1, 0.0f));
                        }
                    }
                    run0 = -1e30f;
                    run1 = -1e30f;
                    first_run = false;
                }
            }
        }
        __syncwarp();   // tbuf/red reused next tile
    }
}

extern "C" void kernel_launch(void* const* d_in, const int* in_sizes, int n_in,
                              void* d_out, int out_size) {
    const float* x   = (const float*)d_in[0];
    const float* pos = (const float*)d_in[1];
    const float* W1  = (const float*)d_in[2];
    const float* b1  = (const float*)d_in[3];
    const float* W2  = (const float*)d_in[4];
    const float* b2  = (const float*)d_in[5];
    const void*  eidx = d_in[6];

    int n_nodes = in_sizes[0] / 13;
    if (n_nodes > NMAX) n_nodes = NMAX;
    long long E = (long long)in_sizes[6] / 2;
    if (E > EMAX - TEDGE) E = EMAX - TEDGE;
    float* out = (float*)d_out;

    int n_tiles = (int)((E + TEDGE - 1) / TEDGE);
    int n_pad = n_tiles * TEDGE - (int)E;
    int nb_nodes = (n_nodes + 255) / 256;
    int nb_edges = (int)((E + 255) / 256);
    int nb_scan  = (n_nodes + 1023) / 1024;
    int n4 = out_size / 4;

    cudaFuncSetAttribute(mma_agg_kernel,
                         cudaFuncAttributeMaxDynamicSharedMemorySize, SMEM_AGG);

    detect_kernel<<<1, 256>>>((const int*)eidx, 2 * E);
    precompute_kernel<<<(n_nodes + 15) / 16, 256>>>(x, pos, W1, b1, n_nodes);
    zero_cnt_kernel<<<nb_nodes, 256>>>(n_nodes);
    zero_out_kernel<<<(n4 + 255) / 256, 256>>>((float4*)out, n4);
    hist_kernel<<<nb_edges, 256>>>(eidx, E);
    scan1_kernel<<<nb_scan, 1024>>>(n_nodes);
    scan2_kernel<<<1, 1024>>>(nb_scan);
    scan3_kernel<<<nb_nodes, 256>>>(n_nodes);
    scatter_kernel<<<nb_edges, 256>>>(eidx, E);
    if (n_pad > 0) pad_kernel<<<1, 256>>>(E, n_pad);
    mma_agg_kernel<<<AGG_GRID, NWARP * 32, SMEM_AGG>>>(W2, b2, out, E, n_tiles);
}